// round 2
// baseline (speedup 1.0000x reference)
#include <cuda_runtime.h>
#include <math.h>

// Problem constants (fixed shapes per reference)
#define CN 100000      // nodes
#define CE 1600000     // edges
#define CG 4096        // graphs
#define CH 128         // hidden
#define CF 32          // input features
#define NB_SCAN 98     // ceil(CN/1024)

// ---------------- device scratch (static, no allocation) ----------------
__device__ __align__(16) int   g_deg[CN];
__device__ __align__(16) int   g_rowptr[CN];
__device__ __align__(16) int   g_cursor[CN];
__device__ __align__(16) int   g_col[CE];
__device__ __align__(16) float g_dinv[CN];
__device__ __align__(16) float g_bufA[(size_t)CN * CH];
__device__ __align__(16) float g_bufB[(size_t)CN * CH];
__device__ __align__(16) float g_sums[6 * CH];     // (sum, sumsq) x 3 layers
__device__ __align__(16) float g_scale[3 * CH];
__device__ __align__(16) float g_shift[3 * CH];
__device__ __align__(16) float g_pooled[CG * CH];
__device__ __align__(16) int   g_cnt[CG];
__device__ __align__(16) int   g_bsums[128];

// ---------------- small helpers ----------------
__device__ __forceinline__ float4 bnrelu4(float4 v, float4 sc, float4 sh) {
    float4 r;
    r.x = fmaxf(fmaf(sc.x, v.x, sh.x), 0.f);
    r.y = fmaxf(fmaf(sc.y, v.y, sh.y), 0.f);
    r.z = fmaxf(fmaf(sc.z, v.z, sh.z), 0.f);
    r.w = fmaxf(fmaf(sc.w, v.w, sh.w), 0.f);
    return r;
}

// ---------------- init ----------------
__global__ void k_zero() {
    int i = blockIdx.x * blockDim.x + threadIdx.x;
    int stride = gridDim.x * blockDim.x;
    for (int j = i; j < CN; j += stride) { g_deg[j] = 0; g_cursor[j] = 0; }
    for (int j = i; j < CG * CH; j += stride) g_pooled[j] = 0.f;
    for (int j = i; j < CG; j += stride) g_cnt[j] = 0;
    for (int j = i; j < 6 * CH; j += stride) g_sums[j] = 0.f;
}

// ---------------- CSR build (edge_index is int32!) ----------------
__global__ void k_deg(const int* __restrict__ ei) {
    int e = blockIdx.x * blockDim.x + threadIdx.x;
    if (e < CE) atomicAdd(&g_deg[ei[CE + e]], 1);
}

__global__ void k_dinv() {
    int v = blockIdx.x * blockDim.x + threadIdx.x;
    if (v < CN) g_dinv[v] = rsqrtf((float)(g_deg[v] + 1));  // +1 self loop
}

__global__ void k_scan1() {
    __shared__ int s[1024];
    int tid = threadIdx.x;
    int i = blockIdx.x * 1024 + tid;
    int v = (i < CN) ? g_deg[i] : 0;
    s[tid] = v;
    __syncthreads();
    for (int off = 1; off < 1024; off <<= 1) {
        int t = (tid >= off) ? s[tid - off] : 0;
        __syncthreads();
        s[tid] += t;
        __syncthreads();
    }
    if (i < CN) g_rowptr[i] = s[tid] - v;   // exclusive within block
    if (tid == 1023) g_bsums[blockIdx.x] = s[1023];
}

__global__ void k_scan2() {
    __shared__ int s[128];
    int tid = threadIdx.x;
    int v = (tid < NB_SCAN) ? g_bsums[tid] : 0;
    s[tid] = v;
    __syncthreads();
    for (int off = 1; off < 128; off <<= 1) {
        int t = (tid >= off) ? s[tid - off] : 0;
        __syncthreads();
        s[tid] += t;
        __syncthreads();
    }
    if (tid < NB_SCAN) g_bsums[tid] = s[tid] - v;  // exclusive block offsets
}

__global__ void k_scan3() {
    int i = blockIdx.x * blockDim.x + threadIdx.x;
    if (i < CN) g_rowptr[i] += g_bsums[i >> 10];
}

__global__ void k_scatter(const int* __restrict__ ei) {
    int e = blockIdx.x * blockDim.x + threadIdx.x;
    if (e < CE) {
        int d = ei[CE + e];
        int p = atomicAdd(&g_cursor[d], 1);
        g_col[g_rowptr[d] + p] = ei[e];
    }
}

// ---------------- aggregation: out = A_norm @ x ----------------
// Layer 0: raw x [N,32], one warp per node, one feature per lane.
__global__ void __launch_bounds__(256) k_agg32(const float* __restrict__ x) {
    int warp = (blockIdx.x * blockDim.x + threadIdx.x) >> 5;
    if (warp >= CN) return;
    int lane = threadIdx.x & 31;
    float dv = g_dinv[warp];
    float acc = dv * dv * x[(size_t)warp * CF + lane];   // self loop
    int e = g_rowptr[warp];
    int e1 = e + g_deg[warp];
    for (; e + 1 < e1; e += 2) {
        int s0 = g_col[e], s1 = g_col[e + 1];
        float w0 = g_dinv[s0] * dv, w1 = g_dinv[s1] * dv;
        float u0 = x[(size_t)s0 * CF + lane];
        float u1 = x[(size_t)s1 * CF + lane];
        acc = fmaf(w0, u0, acc);
        acc = fmaf(w1, u1, acc);
    }
    if (e < e1) {
        int s = g_col[e];
        acc = fmaf(g_dinv[s] * dv, x[(size_t)s * CF + lane], acc);
    }
    g_bufA[(size_t)warp * CF + lane] = acc;
}

// Layers 1/2: input is pre-BN h of previous layer; fuse BN+ReLU into the gather.
__global__ void __launch_bounds__(256) k_agg128(const float* __restrict__ xin,
                                                const float* __restrict__ scale,
                                                const float* __restrict__ shift,
                                                float* __restrict__ out) {
    int warp = (blockIdx.x * blockDim.x + threadIdx.x) >> 5;
    if (warp >= CN) return;
    int lane = threadIdx.x & 31;
    float4 sc = ((const float4*)scale)[lane];
    float4 sh = ((const float4*)shift)[lane];
    float dv = g_dinv[warp];
    float4 v = ((const float4*)(xin + (size_t)warp * CH))[lane];
    v = bnrelu4(v, sc, sh);
    float dv2 = dv * dv;
    float4 acc = make_float4(dv2 * v.x, dv2 * v.y, dv2 * v.z, dv2 * v.w);
    int e = g_rowptr[warp];
    int e1 = e + g_deg[warp];
    for (; e + 1 < e1; e += 2) {
        int s0 = g_col[e], s1 = g_col[e + 1];
        float w0 = g_dinv[s0] * dv, w1 = g_dinv[s1] * dv;
        float4 u0 = ((const float4*)(xin + (size_t)s0 * CH))[lane];
        float4 u1 = ((const float4*)(xin + (size_t)s1 * CH))[lane];
        u0 = bnrelu4(u0, sc, sh);
        u1 = bnrelu4(u1, sc, sh);
        acc.x = fmaf(w0, u0.x, acc.x); acc.y = fmaf(w0, u0.y, acc.y);
        acc.z = fmaf(w0, u0.z, acc.z); acc.w = fmaf(w0, u0.w, acc.w);
        acc.x = fmaf(w1, u1.x, acc.x); acc.y = fmaf(w1, u1.y, acc.y);
        acc.z = fmaf(w1, u1.z, acc.z); acc.w = fmaf(w1, u1.w, acc.w);
    }
    if (e < e1) {
        int s = g_col[e];
        float w = g_dinv[s] * dv;
        float4 u = ((const float4*)(xin + (size_t)s * CH))[lane];
        u = bnrelu4(u, sc, sh);
        acc.x = fmaf(w, u.x, acc.x); acc.y = fmaf(w, u.y, acc.y);
        acc.z = fmaf(w, u.z, acc.z); acc.w = fmaf(w, u.w, acc.w);
    }
    ((float4*)(out + (size_t)warp * CH))[lane] = acc;
}

// ---------------- GEMM: out[N,128] = A[N,K] @ W[K,128] + bias, fused BN stats ----------------
template <int K>
__global__ void __launch_bounds__(256, 2) k_gemm(const float* __restrict__ A,
                                                 const float* __restrict__ W,
                                                 const float* __restrict__ bias,
                                                 float* __restrict__ out,
                                                 float* __restrict__ sums,
                                                 int nrows) {
    extern __shared__ float sm[];
    float* Ws = sm;               // [K][128]
    float* As = sm + K * 128;     // chunk: [32][132] transposed (k-major)
    const int ASTR = 132;
    int tid = threadIdx.x;
    int tx = tid & 15;            // col group
    int ty = tid >> 4;            // row group
    int row0 = blockIdx.x * 128;

    for (int i = tid; i < K * 128; i += 256) Ws[i] = W[i];

    float acc[8][8];
#pragma unroll
    for (int i = 0; i < 8; i++)
#pragma unroll
        for (int j = 0; j < 8; j++) acc[i][j] = 0.f;

    for (int kc = 0; kc < K; kc += 32) {
        __syncthreads();
        for (int i = tid; i < 128 * 32; i += 256) {
            int r = i >> 5, k = i & 31;
            int gr = row0 + r;
            float v = (gr < nrows) ? A[(size_t)gr * K + kc + k] : 0.f;
            As[k * ASTR + r] = v;
        }
        __syncthreads();
#pragma unroll
        for (int k = 0; k < 32; k++) {
            float4 a0 = *(const float4*)&As[k * ASTR + ty * 8];
            float4 a1 = *(const float4*)&As[k * ASTR + ty * 8 + 4];
            float4 b0 = *(const float4*)&Ws[(kc + k) * 128 + tx * 8];
            float4 b1 = *(const float4*)&Ws[(kc + k) * 128 + tx * 8 + 4];
            float av[8] = {a0.x, a0.y, a0.z, a0.w, a1.x, a1.y, a1.z, a1.w};
            float bv[8] = {b0.x, b0.y, b0.z, b0.w, b1.x, b1.y, b1.z, b1.w};
#pragma unroll
            for (int i = 0; i < 8; i++)
#pragma unroll
                for (int j = 0; j < 8; j++) acc[i][j] = fmaf(av[i], bv[j], acc[i][j]);
        }
    }

    // epilogue: + bias, store, per-column partial stats
    float4 bj0 = *(const float4*)&bias[tx * 8];
    float4 bj1 = *(const float4*)&bias[tx * 8 + 4];
    float bj[8] = {bj0.x, bj0.y, bj0.z, bj0.w, bj1.x, bj1.y, bj1.z, bj1.w};
    float csum[8], csq[8];
#pragma unroll
    for (int j = 0; j < 8; j++) { csum[j] = 0.f; csq[j] = 0.f; }
#pragma unroll
    for (int i = 0; i < 8; i++) {
        int r = row0 + ty * 8 + i;
        if (r < nrows) {
            float v[8];
#pragma unroll
            for (int j = 0; j < 8; j++) {
                v[j] = acc[i][j] + bj[j];
                csum[j] += v[j];
                csq[j] += v[j] * v[j];
            }
            float* orow = out + (size_t)r * 128 + tx * 8;
            float4 o0 = make_float4(v[0], v[1], v[2], v[3]);
            float4 o1 = make_float4(v[4], v[5], v[6], v[7]);
            *(float4*)&orow[0] = o0;
            *(float4*)&orow[4] = o1;
        }
    }
    // block reduce stats via smem (reuse Ws region), one atomic per column per block
    __syncthreads();
    float* red = sm;  // 16*128 floats
#pragma unroll
    for (int j = 0; j < 8; j++) red[ty * 128 + tx * 8 + j] = csum[j];
    __syncthreads();
    if (tid < 128) {
        float t = 0.f;
#pragma unroll
        for (int q = 0; q < 16; q++) t += red[q * 128 + tid];
        atomicAdd(&sums[tid], t);
    }
    __syncthreads();
#pragma unroll
    for (int j = 0; j < 8; j++) red[ty * 128 + tx * 8 + j] = csq[j];
    __syncthreads();
    if (tid < 128) {
        float t = 0.f;
#pragma unroll
        for (int q = 0; q < 16; q++) t += red[q * 128 + tid];
        atomicAdd(&sums[128 + tid], t);
    }
}

// ---------------- BN params from stats ----------------
__global__ void k_bnp(const float* __restrict__ sums, const float* __restrict__ g,
                      const float* __restrict__ beta, float* __restrict__ scale,
                      float* __restrict__ shift) {
    int c = threadIdx.x;
    float mean = sums[c] * (1.f / CN);
    float var = sums[128 + c] * (1.f / CN) - mean * mean;
    float sc = g[c] * rsqrtf(var + 1e-5f);
    scale[c] = sc;
    shift[c] = fmaf(-mean, sc, beta[c]);
}

// ---------------- pooling (BN+ReLU fused) ----------------
__global__ void __launch_bounds__(256) k_pool(const int* __restrict__ batch,
                                              const float* __restrict__ scale,
                                              const float* __restrict__ shift) {
    int warp = (blockIdx.x * blockDim.x + threadIdx.x) >> 5;
    if (warp >= CN) return;
    int lane = threadIdx.x & 31;
    float4 sc = ((const float4*)scale)[lane];
    float4 sh = ((const float4*)shift)[lane];
    float4 v = ((const float4*)(g_bufB + (size_t)warp * CH))[lane];
    v = bnrelu4(v, sc, sh);
    int b = batch[warp];
    float* p = &g_pooled[b * CH + lane * 4];
    atomicAdd(p + 0, v.x);
    atomicAdd(p + 1, v.y);
    atomicAdd(p + 2, v.z);
    atomicAdd(p + 3, v.w);
    if (lane == 0) atomicAdd(&g_cnt[b], 1);
}

// ---------------- MLP head ----------------
__global__ void k_head(const float* __restrict__ Wh1, const float* __restrict__ bh1,
                       const float* __restrict__ Wh2, const float* __restrict__ bh2,
                       float* __restrict__ out) {
    __shared__ float row[128];
    __shared__ float red[64];
    int g = blockIdx.x;
    int t = threadIdx.x;  // 64 threads
    float inv = 1.f / fmaxf((float)g_cnt[g], 1.f);
    row[t] = g_pooled[g * CH + t] * inv;
    row[t + 64] = g_pooled[g * CH + 64 + t] * inv;
    __syncthreads();
    float a = bh1[t];
#pragma unroll 8
    for (int f = 0; f < 128; f++) a = fmaf(row[f], Wh1[f * 64 + t], a);
    a = fmaxf(a, 0.f);
    red[t] = a * Wh2[t];
    __syncthreads();
    for (int off = 32; off > 0; off >>= 1) {
        if (t < off) red[t] += red[t + off];
        __syncthreads();
    }
    if (t == 0) out[g] = red[0] + bh2[0];
}

// ---------------- launch ----------------
extern "C" void kernel_launch(void* const* d_in, const int* in_sizes, int n_in,
                              void* d_out, int out_size) {
    const float* x  = (const float*)d_in[0];
    const int* ei   = (const int*)d_in[1];     // int32 (JAX x64 disabled)
    const int* batch= (const int*)d_in[2];     // int32
    const float* W0 = (const float*)d_in[3];
    const float* b0 = (const float*)d_in[4];
    const float* g0 = (const float*)d_in[5];
    const float* be0= (const float*)d_in[6];
    const float* W1 = (const float*)d_in[7];
    const float* b1 = (const float*)d_in[8];
    const float* g1 = (const float*)d_in[9];
    const float* be1= (const float*)d_in[10];
    const float* W2 = (const float*)d_in[11];
    const float* b2 = (const float*)d_in[12];
    const float* g2 = (const float*)d_in[13];
    const float* be2= (const float*)d_in[14];
    const float* Wh1= (const float*)d_in[15];
    const float* bh1= (const float*)d_in[16];
    const float* Wh2= (const float*)d_in[17];
    const float* bh2= (const float*)d_in[18];
    float* out = (float*)d_out;

    void* p;
    cudaGetSymbolAddress(&p, g_bufA);   float* bufA  = (float*)p;
    cudaGetSymbolAddress(&p, g_bufB);   float* bufB  = (float*)p;
    cudaGetSymbolAddress(&p, g_sums);   float* sums  = (float*)p;
    cudaGetSymbolAddress(&p, g_scale);  float* scale = (float*)p;
    cudaGetSymbolAddress(&p, g_shift);  float* shift = (float*)p;

    const int SM128 = (128 * 128 + 32 * 132) * 4;  // 82432 B
    const int SM32  = (32 * 128 + 32 * 132) * 4;   // 33280 B
    cudaFuncSetAttribute(k_gemm<128>, cudaFuncAttributeMaxDynamicSharedMemorySize, SM128);
    cudaFuncSetAttribute(k_gemm<32>,  cudaFuncAttributeMaxDynamicSharedMemorySize, SM32);

    const int gemmBlocks = (CN + 127) / 128;   // 782
    const int aggBlocks = (CN + 7) / 8;        // 12500 (8 warps/block)

    k_zero<<<512, 256>>>();
    k_deg<<<(CE + 255) / 256, 256>>>(ei);
    k_dinv<<<(CN + 255) / 256, 256>>>();
    k_scan1<<<NB_SCAN, 1024>>>();
    k_scan2<<<1, 128>>>();
    k_scan3<<<(CN + 255) / 256, 256>>>();
    k_scatter<<<(CE + 255) / 256, 256>>>(ei);

    // Layer 0: aggregate raw x (F=32) then GEMM -> bufB (pre-BN h0) + stats
    k_agg32<<<aggBlocks, 256>>>(x);
    k_gemm<32><<<gemmBlocks, 256, SM32>>>(bufA, W0, b0, bufB, sums, CN);
    k_bnp<<<1, 128>>>(sums, g0, be0, scale, shift);

    // Layer 1
    k_agg128<<<aggBlocks, 256>>>(bufB, scale, shift, bufA);
    k_gemm<128><<<gemmBlocks, 256, SM128>>>(bufA, W1, b1, bufB, sums + 256, CN);
    k_bnp<<<1, 128>>>(sums + 256, g1, be1, scale + 128, shift + 128);

    // Layer 2
    k_agg128<<<aggBlocks, 256>>>(bufB, scale + 128, shift + 128, bufA);
    k_gemm<128><<<gemmBlocks, 256, SM128>>>(bufA, W2, b2, bufB, sums + 512, CN);
    k_bnp<<<1, 128>>>(sums + 512, g2, be2, scale + 256, shift + 256);

    // Pool + head
    k_pool<<<aggBlocks, 256>>>(batch, scale + 256, shift + 256);
    k_head<<<CG, 64>>>(Wh1, bh1, Wh2, bh2, out);
}

// round 3
// speedup vs baseline: 1.1140x; 1.1140x over previous
#include <cuda_runtime.h>
#include <math.h>

// Problem constants (fixed shapes per reference)
#define CN 100000      // nodes
#define CE 1600000     // edges
#define CG 4096        // graphs
#define CH 128         // hidden
#define CF 32          // input features
#define NB_SCAN 98     // ceil(CN/1024)

// ---------------- device scratch (static, no allocation) ----------------
__device__ __align__(16) int   g_deg[CN];
__device__ __align__(16) int   g_rowptr[CN];
__device__ __align__(16) int   g_cursor[CN];
__device__ __align__(16) int   g_col[CE];
__device__ __align__(16) float g_dinv[CN];
__device__ __align__(16) float g_bufA[(size_t)CN * CH];
__device__ __align__(16) float g_bufB[(size_t)CN * CH];
__device__ __align__(16) float g_sums[6 * CH];     // (sum, sumsq) x 3 layers
__device__ __align__(16) float g_scale[3 * CH];
__device__ __align__(16) float g_shift[3 * CH];
__device__ __align__(16) int   g_bsums[128];

// ---------------- packed fp32x2 helpers (Blackwell full-rate fp32 path) ----------------
__device__ __forceinline__ unsigned long long pack2(float lo, float hi) {
    unsigned long long r;
    asm("mov.b64 %0, {%1, %2};" : "=l"(r) : "f"(lo), "f"(hi));
    return r;
}
__device__ __forceinline__ void unpack2(unsigned long long v, float& lo, float& hi) {
    asm("mov.b64 {%0, %1}, %2;" : "=f"(lo), "=f"(hi) : "l"(v));
}
__device__ __forceinline__ void ffma2(unsigned long long& d, unsigned long long a,
                                      unsigned long long b) {
    asm("fma.rn.f32x2 %0, %1, %2, %0;" : "+l"(d) : "l"(a), "l"(b));
}

// ---------------- small helpers ----------------
__device__ __forceinline__ float4 bnrelu4(float4 v, float4 sc, float4 sh) {
    float4 r;
    r.x = fmaxf(fmaf(sc.x, v.x, sh.x), 0.f);
    r.y = fmaxf(fmaf(sc.y, v.y, sh.y), 0.f);
    r.z = fmaxf(fmaf(sc.z, v.z, sh.z), 0.f);
    r.w = fmaxf(fmaf(sc.w, v.w, sh.w), 0.f);
    return r;
}

// ---------------- init ----------------
__global__ void k_zero() {
    int i = blockIdx.x * blockDim.x + threadIdx.x;
    int stride = gridDim.x * blockDim.x;
    for (int j = i; j < CN; j += stride) { g_deg[j] = 0; g_cursor[j] = 0; }
    for (int j = i; j < 6 * CH; j += stride) g_sums[j] = 0.f;
}

// ---------------- CSR build (edge_index is int32) ----------------
__global__ void k_deg(const int* __restrict__ ei) {
    int e = blockIdx.x * blockDim.x + threadIdx.x;
    if (e < CE) atomicAdd(&g_deg[ei[CE + e]], 1);
}

__global__ void k_scan1() {     // also produces dinv
    __shared__ int s[1024];
    int tid = threadIdx.x;
    int i = blockIdx.x * 1024 + tid;
    int v = (i < CN) ? g_deg[i] : 0;
    if (i < CN) g_dinv[i] = rsqrtf((float)(v + 1));   // +1 self loop
    s[tid] = v;
    __syncthreads();
    for (int off = 1; off < 1024; off <<= 1) {
        int t = (tid >= off) ? s[tid - off] : 0;
        __syncthreads();
        s[tid] += t;
        __syncthreads();
    }
    if (i < CN) g_rowptr[i] = s[tid] - v;   // exclusive within block
    if (tid == 1023) g_bsums[blockIdx.x] = s[1023];
}

__global__ void k_scan2() {
    __shared__ int s[128];
    int tid = threadIdx.x;
    int v = (tid < NB_SCAN) ? g_bsums[tid] : 0;
    s[tid] = v;
    __syncthreads();
    for (int off = 1; off < 128; off <<= 1) {
        int t = (tid >= off) ? s[tid - off] : 0;
        __syncthreads();
        s[tid] += t;
        __syncthreads();
    }
    if (tid < NB_SCAN) g_bsums[tid] = s[tid] - v;  // exclusive block offsets
}

__global__ void k_scan3() {
    int i = blockIdx.x * blockDim.x + threadIdx.x;
    if (i < CN) g_rowptr[i] += g_bsums[i >> 10];
}

__global__ void k_scatter(const int* __restrict__ ei) {
    int e = blockIdx.x * blockDim.x + threadIdx.x;
    if (e < CE) {
        int d = ei[CE + e];
        int p = atomicAdd(&g_cursor[d], 1);
        g_col[g_rowptr[d] + p] = ei[e];
    }
}

// ---------------- aggregation: out = A_norm @ x ----------------
// Layer 0: raw x [N,32], one warp per node, one feature per lane.
__global__ void __launch_bounds__(256) k_agg32(const float* __restrict__ x) {
    int warp = (blockIdx.x * blockDim.x + threadIdx.x) >> 5;
    if (warp >= CN) return;
    int lane = threadIdx.x & 31;
    float dv = g_dinv[warp];
    float acc = dv * dv * x[(size_t)warp * CF + lane];   // self loop
    int e = g_rowptr[warp];
    int e1 = e + g_deg[warp];
    for (; e + 3 < e1; e += 4) {
        int s0 = g_col[e], s1 = g_col[e + 1], s2 = g_col[e + 2], s3 = g_col[e + 3];
        float w0 = g_dinv[s0] * dv, w1 = g_dinv[s1] * dv;
        float w2 = g_dinv[s2] * dv, w3 = g_dinv[s3] * dv;
        float u0 = x[(size_t)s0 * CF + lane];
        float u1 = x[(size_t)s1 * CF + lane];
        float u2 = x[(size_t)s2 * CF + lane];
        float u3 = x[(size_t)s3 * CF + lane];
        acc = fmaf(w0, u0, acc);
        acc = fmaf(w1, u1, acc);
        acc = fmaf(w2, u2, acc);
        acc = fmaf(w3, u3, acc);
    }
    for (; e < e1; e++) {
        int s = g_col[e];
        acc = fmaf(g_dinv[s] * dv, x[(size_t)s * CF + lane], acc);
    }
    g_bufA[(size_t)warp * CF + lane] = acc;
}

// Layers 1/2: input is pre-BN h of previous layer; fuse BN+ReLU into the gather.
__global__ void __launch_bounds__(256) k_agg128(const float* __restrict__ xin,
                                                const float* __restrict__ scale,
                                                const float* __restrict__ shift,
                                                float* __restrict__ out) {
    int warp = (blockIdx.x * blockDim.x + threadIdx.x) >> 5;
    if (warp >= CN) return;
    int lane = threadIdx.x & 31;
    float4 sc = ((const float4*)scale)[lane];
    float4 sh = ((const float4*)shift)[lane];
    float dv = g_dinv[warp];
    float4 v = ((const float4*)(xin + (size_t)warp * CH))[lane];
    v = bnrelu4(v, sc, sh);
    float dv2 = dv * dv;
    float4 acc = make_float4(dv2 * v.x, dv2 * v.y, dv2 * v.z, dv2 * v.w);
    int e = g_rowptr[warp];
    int e1 = e + g_deg[warp];
    for (; e + 1 < e1; e += 2) {
        int s0 = g_col[e], s1 = g_col[e + 1];
        float w0 = g_dinv[s0] * dv, w1 = g_dinv[s1] * dv;
        float4 u0 = ((const float4*)(xin + (size_t)s0 * CH))[lane];
        float4 u1 = ((const float4*)(xin + (size_t)s1 * CH))[lane];
        u0 = bnrelu4(u0, sc, sh);
        u1 = bnrelu4(u1, sc, sh);
        acc.x = fmaf(w0, u0.x, acc.x); acc.y = fmaf(w0, u0.y, acc.y);
        acc.z = fmaf(w0, u0.z, acc.z); acc.w = fmaf(w0, u0.w, acc.w);
        acc.x = fmaf(w1, u1.x, acc.x); acc.y = fmaf(w1, u1.y, acc.y);
        acc.z = fmaf(w1, u1.z, acc.z); acc.w = fmaf(w1, u1.w, acc.w);
    }
    if (e < e1) {
        int s = g_col[e];
        float w = g_dinv[s] * dv;
        float4 u = ((const float4*)(xin + (size_t)s * CH))[lane];
        u = bnrelu4(u, sc, sh);
        acc.x = fmaf(w, u.x, acc.x); acc.y = fmaf(w, u.y, acc.y);
        acc.z = fmaf(w, u.z, acc.z); acc.w = fmaf(w, u.w, acc.w);
    }
    ((float4*)(out + (size_t)warp * CH))[lane] = acc;
}

// ---------------- GEMM: out[N,128] = A[N,K] @ W[K,128] + bias, fused BN stats ----
// Inner loop uses packed fp32x2 FFMA (full-rate fp32 on Blackwell).
template <int K>
__global__ void __launch_bounds__(256, 2) k_gemm(const float* __restrict__ A,
                                                 const float* __restrict__ W,
                                                 const float* __restrict__ bias,
                                                 float* __restrict__ out,
                                                 float* __restrict__ sums,
                                                 int nrows) {
    extern __shared__ float sm[];
    float* Ws = sm;               // [K][128]
    float* As = sm + K * 128;     // chunk: [32][132] transposed (k-major)
    const int ASTR = 132;
    int tid = threadIdx.x;
    int tx = tid & 15;            // col group
    int ty = tid >> 4;            // row group
    int row0 = blockIdx.x * 128;

    for (int i = tid; i < K * 128; i += 256) Ws[i] = W[i];

    unsigned long long acc[8][4];   // 8 rows x 4 col-pairs (f32x2)
#pragma unroll
    for (int i = 0; i < 8; i++)
#pragma unroll
        for (int j = 0; j < 4; j++) acc[i][j] = 0ull;

    for (int kc = 0; kc < K; kc += 32) {
        __syncthreads();
        for (int i = tid; i < 128 * 32; i += 256) {
            int r = i >> 5, k = i & 31;
            int gr = row0 + r;
            float v = (gr < nrows) ? A[(size_t)gr * K + kc + k] : 0.f;
            As[k * ASTR + r] = v;
        }
        __syncthreads();
#pragma unroll
        for (int k = 0; k < 32; k++) {
            float4 a0 = *(const float4*)&As[k * ASTR + ty * 8];
            float4 a1 = *(const float4*)&As[k * ASTR + ty * 8 + 4];
            float4 b0 = *(const float4*)&Ws[(kc + k) * 128 + tx * 8];
            float4 b1 = *(const float4*)&Ws[(kc + k) * 128 + tx * 8 + 4];
            unsigned long long bp[4];
            bp[0] = pack2(b0.x, b0.y);
            bp[1] = pack2(b0.z, b0.w);
            bp[2] = pack2(b1.x, b1.y);
            bp[3] = pack2(b1.z, b1.w);
            float av[8] = {a0.x, a0.y, a0.z, a0.w, a1.x, a1.y, a1.z, a1.w};
#pragma unroll
            for (int i = 0; i < 8; i++) {
                unsigned long long ap = pack2(av[i], av[i]);
#pragma unroll
                for (int j = 0; j < 4; j++) ffma2(acc[i][j], ap, bp[j]);
            }
        }
    }

    // epilogue: + bias, store, per-column partial stats
    float4 bj0 = *(const float4*)&bias[tx * 8];
    float4 bj1 = *(const float4*)&bias[tx * 8 + 4];
    float bj[8] = {bj0.x, bj0.y, bj0.z, bj0.w, bj1.x, bj1.y, bj1.z, bj1.w};
    float csum[8], csq[8];
#pragma unroll
    for (int j = 0; j < 8; j++) { csum[j] = 0.f; csq[j] = 0.f; }
#pragma unroll
    for (int i = 0; i < 8; i++) {
        int r = row0 + ty * 8 + i;
        if (r < nrows) {
            float v[8];
#pragma unroll
            for (int j = 0; j < 4; j++) unpack2(acc[i][j], v[2 * j], v[2 * j + 1]);
#pragma unroll
            for (int j = 0; j < 8; j++) {
                v[j] += bj[j];
                csum[j] += v[j];
                csq[j] += v[j] * v[j];
            }
            float* orow = out + (size_t)r * 128 + tx * 8;
            *(float4*)&orow[0] = make_float4(v[0], v[1], v[2], v[3]);
            *(float4*)&orow[4] = make_float4(v[4], v[5], v[6], v[7]);
        }
    }
    // block reduce stats via smem (reuse Ws region), one atomic per column per block
    __syncthreads();
    float* red = sm;  // 16*128 floats
#pragma unroll
    for (int j = 0; j < 8; j++) red[ty * 128 + tx * 8 + j] = csum[j];
    __syncthreads();
    if (tid < 128) {
        float t = 0.f;
#pragma unroll
        for (int q = 0; q < 16; q++) t += red[q * 128 + tid];
        atomicAdd(&sums[tid], t);
    }
    __syncthreads();
#pragma unroll
    for (int j = 0; j < 8; j++) red[ty * 128 + tx * 8 + j] = csq[j];
    __syncthreads();
    if (tid < 128) {
        float t = 0.f;
#pragma unroll
        for (int q = 0; q < 16; q++) t += red[q * 128 + tid];
        atomicAdd(&sums[128 + tid], t);
    }
}

// ---------------- BN params from stats ----------------
__global__ void k_bnp(const float* __restrict__ sums, const float* __restrict__ g,
                      const float* __restrict__ beta, float* __restrict__ scale,
                      float* __restrict__ shift) {
    int c = threadIdx.x;
    float mean = sums[c] * (1.f / CN);
    float var = sums[128 + c] * (1.f / CN) - mean * mean;
    float sc = g[c] * rsqrtf(var + 1e-5f);
    scale[c] = sc;
    shift[c] = fmaf(-mean, sc, beta[c]);
}

// ---------------- fused pooling + MLP head (batch is sorted) ----------------
__global__ void __launch_bounds__(128) k_poolhead(const int* __restrict__ batch,
                                                  const float* __restrict__ scale,
                                                  const float* __restrict__ shift,
                                                  const float* __restrict__ Wh1,
                                                  const float* __restrict__ bh1,
                                                  const float* __restrict__ Wh2,
                                                  const float* __restrict__ bh2,
                                                  float* __restrict__ out) {
    __shared__ float row[128];
    __shared__ float red[64];
    int g = blockIdx.x;
    int t = threadIdx.x;  // 128 threads

    // lower_bound(batch, g) and lower_bound(batch, g+1)
    int lo = 0, hi = CN;
    while (lo < hi) { int m = (lo + hi) >> 1; if (batch[m] < g) lo = m + 1; else hi = m; }
    int start = lo;
    hi = CN;
    while (lo < hi) { int m = (lo + hi) >> 1; if (batch[m] < g + 1) lo = m + 1; else hi = m; }
    int end = lo;

    float sc = scale[t], sh = shift[t];
    float acc = 0.f;
    for (int i = start; i < end; i++)
        acc += fmaxf(fmaf(sc, g_bufB[(size_t)i * CH + t], sh), 0.f);
    float inv = 1.f / fmaxf((float)(end - start), 1.f);
    row[t] = acc * inv;
    __syncthreads();

    if (t < 64) {
        float a = bh1[t];
#pragma unroll 8
        for (int f = 0; f < 128; f++) a = fmaf(row[f], Wh1[f * 64 + t], a);
        a = fmaxf(a, 0.f);
        red[t] = a * Wh2[t];
    }
    __syncthreads();
    if (t < 32) {
        float v = red[t] + red[t + 32];
#pragma unroll
        for (int off = 16; off > 0; off >>= 1)
            v += __shfl_down_sync(0xffffffffu, v, off);
        if (t == 0) out[g] = v + bh2[0];
    }
}

// ---------------- launch ----------------
extern "C" void kernel_launch(void* const* d_in, const int* in_sizes, int n_in,
                              void* d_out, int out_size) {
    const float* x  = (const float*)d_in[0];
    const int* ei   = (const int*)d_in[1];     // int32 (JAX x64 disabled)
    const int* batch= (const int*)d_in[2];     // int32
    const float* W0 = (const float*)d_in[3];
    const float* b0 = (const float*)d_in[4];
    const float* g0 = (const float*)d_in[5];
    const float* be0= (const float*)d_in[6];
    const float* W1 = (const float*)d_in[7];
    const float* b1 = (const float*)d_in[8];
    const float* g1 = (const float*)d_in[9];
    const float* be1= (const float*)d_in[10];
    const float* W2 = (const float*)d_in[11];
    const float* b2 = (const float*)d_in[12];
    const float* g2 = (const float*)d_in[13];
    const float* be2= (const float*)d_in[14];
    const float* Wh1= (const float*)d_in[15];
    const float* bh1= (const float*)d_in[16];
    const float* Wh2= (const float*)d_in[17];
    const float* bh2= (const float*)d_in[18];
    float* out = (float*)d_out;

    void* p;
    cudaGetSymbolAddress(&p, g_bufA);   float* bufA  = (float*)p;
    cudaGetSymbolAddress(&p, g_bufB);   float* bufB  = (float*)p;
    cudaGetSymbolAddress(&p, g_sums);   float* sums  = (float*)p;
    cudaGetSymbolAddress(&p, g_scale);  float* scale = (float*)p;
    cudaGetSymbolAddress(&p, g_shift);  float* shift = (float*)p;

    const int SM128 = (128 * 128 + 32 * 132) * 4;  // 82432 B
    const int SM32  = (32 * 128 + 32 * 132) * 4;   // 33280 B
    cudaFuncSetAttribute(k_gemm<128>, cudaFuncAttributeMaxDynamicSharedMemorySize, SM128);
    cudaFuncSetAttribute(k_gemm<32>,  cudaFuncAttributeMaxDynamicSharedMemorySize, SM32);

    const int gemmBlocks = (CN + 127) / 128;   // 782
    const int aggBlocks = (CN + 7) / 8;        // 12500 (8 warps/block)

    k_zero<<<512, 256>>>();
    k_deg<<<(CE + 255) / 256, 256>>>(ei);
    k_scan1<<<NB_SCAN, 1024>>>();
    k_scan2<<<1, 128>>>();
    k_scan3<<<(CN + 255) / 256, 256>>>();
    k_scatter<<<(CE + 255) / 256, 256>>>(ei);

    // Layer 0: aggregate raw x (F=32) then GEMM -> bufB (pre-BN h0) + stats
    k_agg32<<<aggBlocks, 256>>>(x);
    k_gemm<32><<<gemmBlocks, 256, SM32>>>(bufA, W0, b0, bufB, sums, CN);
    k_bnp<<<1, 128>>>(sums, g0, be0, scale, shift);

    // Layer 1
    k_agg128<<<aggBlocks, 256>>>(bufB, scale, shift, bufA);
    k_gemm<128><<<gemmBlocks, 256, SM128>>>(bufA, W1, b1, bufB, sums + 256, CN);
    k_bnp<<<1, 128>>>(sums + 256, g1, be1, scale + 128, shift + 128);

    // Layer 2
    k_agg128<<<aggBlocks, 256>>>(bufB, scale + 128, shift + 128, bufA);
    k_gemm<128><<<gemmBlocks, 256, SM128>>>(bufA, W2, b2, bufB, sums + 512, CN);
    k_bnp<<<1, 128>>>(sums + 512, g2, be2, scale + 256, shift + 256);

    // Fused pool + head (no atomics; batch is sorted)
    k_poolhead<<<CG, 128>>>(batch, scale + 256, shift + 256, Wh1, bh1, Wh2, bh2, out);
}